// round 13
// baseline (speedup 1.0000x reference)
#include <cuda_runtime.h>
#include <cuda_bf16.h>
#include <cstdint>

#define NTOK 32768
#define NEXP 64
#define CDIM 1024
#define CAPV 2048

#define BM 128
#define BK 16
#define NCH (CDIM / BK)     // 64 chunks
#define THREADS 256

// smem stage (fp32 words): A k-major [16][132], B duplicated [16][136]
#define ASTR 132
#define BSTRD 136
#define A_WORDS (BK * ASTR)             // 2112
#define STAGE_W (A_WORDS + BK * BSTRD)  // 2112 + 2176 = 4288 words (17152 B)

__device__ int g_top[2 * NTOK];

typedef unsigned long long u64;

// ---------------------------------------------------------------------------
__device__ __forceinline__ void fma2(u64& d, u64 a, u64 b) {
    asm("fma.rn.f32x2 %0, %1, %2, %0;" : "+l"(d) : "l"(a), "l"(b));
}
__device__ __forceinline__ void unpack2(u64 v, float& lo, float& hi) {
    uint32_t l, h;
    asm("mov.b64 {%0, %1}, %2;" : "=r"(l), "=r"(h) : "l"(v));
    lo = __uint_as_float(l);
    hi = __uint_as_float(h);
}

// ---------------------------------------------------------------------------
// Kernel 1: fused FFMA2 GEMM (M=32768,N=64,K=1024) + top-2 + softmax.
// 8 warps. warp -> experts wid*8..+7 (B smem broadcast, stored DUPLICATED so
// LDS.128 yields (b,b) u64 operands). lane -> rows 4*lane..4*lane+3, A k-major
// so LDS.128 yields two row-pair u64 operands. Zero pack MOVs in inner loop.
// Double-buffered smem fed by register prefetch (distance 2).
// ---------------------------------------------------------------------------
__global__ __launch_bounds__(THREADS) void gemm_top2_kernel(
    const float* __restrict__ x, const float* __restrict__ w,
    float* __restrict__ out_probs, float* __restrict__ out_idx)
{
    __shared__ __align__(16) float sm[2 * STAGE_W];

    const int tid  = threadIdx.x;
    const int wid  = tid >> 5;
    const int lane = tid & 31;
    const int row0 = blockIdx.x * BM;

    // LDG mappings
    // A: 512 16B-chunks per stage; id = row*4 + q, thread covers id=tid, tid+256
    const int ar0 = tid >> 2;            // row of first chunk
    const int aq0 = tid & 3;             // 16B segment within row (k = q*4..q*4+3)
    const int ar1 = (tid + 256) >> 2;
    const int aq1 = (tid + 256) & 3;
    // B: be = expert, bk = k offset {0,4,8,12}
    const int be = tid >> 2;
    const int bk = (tid & 3) * 4;

    const float* xp0 = x + (size_t)(row0 + ar0) * CDIM + aq0 * 4;
    const float* xp1 = x + (size_t)(row0 + ar1) * CDIM + aq1 * 4;
    const float* wp  = w + (size_t)be * CDIM + bk;

    float4 rA0, rA1, rB;

    auto ldg = [&](int c) {
        rA0 = *reinterpret_cast<const float4*>(xp0 + c * BK);
        rA1 = *reinterpret_cast<const float4*>(xp1 + c * BK);
        rB  = *reinterpret_cast<const float4*>(wp + c * BK);
    };
    auto sts = [&](int s) {
        float* st = sm + s * STAGE_W;
        st[(aq0 * 4 + 0) * ASTR + ar0] = rA0.x;
        st[(aq0 * 4 + 1) * ASTR + ar0] = rA0.y;
        st[(aq0 * 4 + 2) * ASTR + ar0] = rA0.z;
        st[(aq0 * 4 + 3) * ASTR + ar0] = rA0.w;
        st[(aq1 * 4 + 0) * ASTR + ar1] = rA1.x;
        st[(aq1 * 4 + 1) * ASTR + ar1] = rA1.y;
        st[(aq1 * 4 + 2) * ASTR + ar1] = rA1.z;
        st[(aq1 * 4 + 3) * ASTR + ar1] = rA1.w;
        float* bt = st + A_WORDS;
        *reinterpret_cast<float2*>(bt + (bk + 0) * BSTRD + 2 * be) = make_float2(rB.x, rB.x);
        *reinterpret_cast<float2*>(bt + (bk + 1) * BSTRD + 2 * be) = make_float2(rB.y, rB.y);
        *reinterpret_cast<float2*>(bt + (bk + 2) * BSTRD + 2 * be) = make_float2(rB.z, rB.z);
        *reinterpret_cast<float2*>(bt + (bk + 3) * BSTRD + 2 * be) = make_float2(rB.w, rB.w);
    };

    u64 acc[2][8];
#pragma unroll
    for (int p = 0; p < 2; p++)
#pragma unroll
        for (int j = 0; j < 8; j++) acc[p][j] = 0ull;

    // prologue: stage0 <- chunk0 ; regs <- chunk1
    ldg(0);
    sts(0);
    ldg(1);

#pragma unroll 1
    for (int c = 0; c < NCH; c++) {
        if (c + 1 < NCH) sts((c + 1) & 1);          // regs hold chunk c+1
        if (c + 2 < NCH) ldg(c + 2);
        __syncthreads();                             // publish stage[c&1]

        const float* st = sm + (c & 1) * STAGE_W;
        const float* bt = st + A_WORDS + wid * 16;

#pragma unroll
        for (int k = 0; k < BK; k++) {
            ulonglong2 a  = *reinterpret_cast<const ulonglong2*>(st + k * ASTR + 4 * lane);
            ulonglong2 b0 = *reinterpret_cast<const ulonglong2*>(bt + k * BSTRD);
            ulonglong2 b1 = *reinterpret_cast<const ulonglong2*>(bt + k * BSTRD + 4);
            ulonglong2 b2 = *reinterpret_cast<const ulonglong2*>(bt + k * BSTRD + 8);
            ulonglong2 b3 = *reinterpret_cast<const ulonglong2*>(bt + k * BSTRD + 12);
            fma2(acc[0][0], a.x, b0.x); fma2(acc[1][0], a.y, b0.x);
            fma2(acc[0][1], a.x, b0.y); fma2(acc[1][1], a.y, b0.y);
            fma2(acc[0][2], a.x, b1.x); fma2(acc[1][2], a.y, b1.x);
            fma2(acc[0][3], a.x, b1.y); fma2(acc[1][3], a.y, b1.y);
            fma2(acc[0][4], a.x, b2.x); fma2(acc[1][4], a.y, b2.x);
            fma2(acc[0][5], a.x, b2.y); fma2(acc[1][5], a.y, b2.y);
            fma2(acc[0][6], a.x, b3.x); fma2(acc[1][6], a.y, b3.x);
            fma2(acc[0][7], a.x, b3.y); fma2(acc[1][7], a.y, b3.y);
        }
        __syncthreads();                             // all done reading stage[c&1]
    }

    // --- per-warp local top-2 (experts wid*8..+7), ascending-index ties ---
    // rows of this thread: 4*lane + r; r=0,1 from acc[0][j] lo/hi, r=2,3 from acc[1][j]
#pragma unroll
    for (int p = 0; p < 2; p++) {
        float vlo[8], vhi[8];
#pragma unroll
        for (int j = 0; j < 8; j++) unpack2(acc[p][j], vlo[j], vhi[j]);
#pragma unroll
        for (int h = 0; h < 2; h++) {
            const float* v = h ? vhi : vlo;
            float a1 = v[0], a2 = -3.4e38f;
            int j1 = wid * 8, j2 = wid * 8;
#pragma unroll
            for (int j = 1; j < 8; j++) {
                float vv = v[j];
                int jj = wid * 8 + j;
                if (vv > a1)      { a2 = a1; j2 = j1; a1 = vv; j1 = jj; }
                else if (vv > a2) { a2 = vv; j2 = jj; }
            }
            int row = 4 * lane + 2 * p + h;
            float4 cand = make_float4(a1, a2, __int_as_float(j1), __int_as_float(j2));
            *reinterpret_cast<float4*>(sm + (size_t)(row * 9 + wid) * 4) = cand;
        }
    }
    __syncthreads();

    // --- merge 8 warp candidates per row; threads 0..127, one row each ---
    if (tid < BM) {
        const float4* cbase = reinterpret_cast<const float4*>(sm) + tid * 9;
        float4 c0 = cbase[0];
        float best1 = c0.x, best2 = c0.y;
        int   j1 = __float_as_int(c0.z), j2 = __float_as_int(c0.w);
#pragma unroll
        for (int wv = 1; wv < 8; wv++) {
            float4 cw = cbase[wv];
            float b1 = cw.x, b2 = cw.y;
            int   k1 = __float_as_int(cw.z), k2 = __float_as_int(cw.w);
            if (b1 > best1) {
                if (b2 > best1) { best2 = b2; j2 = k2; }
                else            { best2 = best1; j2 = j1; }
                best1 = b1; j1 = k1;
            } else if (b1 > best2) {
                best2 = b1; j2 = k1;
            }
        }
        int t = row0 + tid;
        float ed = __expf(best2 - best1);
        float p1 = 1.0f / (1.0f + ed);
        float p2 = ed / (1.0f + ed);
        g_top[t]        = j1;
        g_top[NTOK + t] = j2;
        out_probs[2 * t]     = p1;
        out_probs[2 * t + 1] = p2;
        out_idx[2 * t]       = (float)j1;
        out_idx[2 * t + 1]   = (float)j2;
    }
}

// ---------------------------------------------------------------------------
// Kernel 2: rank/capacity, single pass. 128 CTAs: bid>>1 = expert, bid&1 = s.
// Thread owns 32 contiguous tokens (8x int4, MLP=8). One fused block scan:
// low 16 bits = own-stream count (scanned), high 16 = stream0 count (reduced,
// only needed for s=1 carry). Then register-resident ordered walk.
// ---------------------------------------------------------------------------
__global__ __launch_bounds__(1024) void rank_kernel(
    float* __restrict__ out_mask, float* __restrict__ out_probs,
    float* __restrict__ out_rank)
{
    const int e    = blockIdx.x >> 1;
    const int s    = blockIdx.x & 1;
    const int tid  = threadIdx.x;
    const int lane = tid & 31;
    const int wid  = tid >> 5;

    __shared__ uint32_t wsum[32];
    __shared__ uint32_t tot_sh;

    // load my 32 tokens of stream s
    int4 v[8];
    const int4* ps = reinterpret_cast<const int4*>(g_top + s * NTOK);
#pragma unroll
    for (int i = 0; i < 8; i++) v[i] = ps[tid * 8 + i];

    uint32_t cnt = 0;
#pragma unroll
    for (int i = 0; i < 8; i++)
        cnt += (v[i].x == e) + (v[i].y == e) + (v[i].z == e) + (v[i].w == e);

    uint32_t c0 = 0;
    if (s) {
        const int4* p0 = reinterpret_cast<const int4*>(g_top);
#pragma unroll
        for (int i = 0; i < 8; i++) {
            int4 u = p0[tid * 8 + i];
            c0 += (u.x == e) + (u.y == e) + (u.z == e) + (u.w == e);
        }
    }

    uint32_t comb = cnt | (c0 << 16);
    uint32_t inc = comb;
#pragma unroll
    for (int o = 1; o < 32; o <<= 1) {
        uint32_t t2 = __shfl_up_sync(0xffffffffu, inc, o);
        if (lane >= o) inc += t2;
    }
    if (lane == 31) wsum[wid] = inc;
    __syncthreads();
    if (wid == 0) {
        uint32_t wv = wsum[lane];
        uint32_t winc = wv;
#pragma unroll
        for (int o = 1; o < 32; o <<= 1) {
            uint32_t t2 = __shfl_up_sync(0xffffffffu, winc, o);
            if (lane >= o) winc += t2;
        }
        wsum[lane] = winc - wv;            // exclusive warp offsets
        if (lane == 31) tot_sh = winc;     // block totals (both fields)
    }
    __syncthreads();

    uint32_t excl = wsum[wid] + (inc - comb);
    int r = (int)(excl & 0xffffu) + (s ? (int)(tot_sh >> 16) : 0);

#pragma unroll
    for (int i = 0; i < 8; i++) {
        int tk = tid * 32 + i * 4;
        int vals[4] = {v[i].x, v[i].y, v[i].z, v[i].w};
#pragma unroll
        for (int j = 0; j < 4; j++) {
            if (vals[j] == e) {
                int oi = (tk + j) * 2 + s;
                out_rank[oi] = (float)r;
                if (r < CAPV) out_mask[(size_t)oi * NEXP + e] = 1.0f;
                else out_probs[oi] = 0.0f;
                r++;
            }
        }
    }
}

// ---------------------------------------------------------------------------
extern "C" void kernel_launch(void* const* d_in, const int* in_sizes, int n_in,
                              void* d_out, int out_size)
{
    const float* x = (const float*)d_in[0];
    const float* w = (const float*)d_in[1];

    float* out       = (float*)d_out;
    float* out_mask  = out;                                   // N*2*64
    float* out_probs = out + (size_t)NTOK * 2 * NEXP;         // N*2
    float* out_idx   = out_probs + NTOK * 2;                  // N*2
    float* out_rank  = out_idx + NTOK * 2;                    // N*2

    cudaMemsetAsync(out_mask, 0, (size_t)NTOK * 2 * NEXP * sizeof(float));
    gemm_top2_kernel<<<NTOK / BM, THREADS>>>(x, w, out_probs, out_idx);
    rank_kernel<<<2 * NEXP, 1024>>>(out_mask, out_probs, out_rank);
}

// round 16
// speedup vs baseline: 1.0958x; 1.0958x over previous
#include <cuda_runtime.h>
#include <cuda_bf16.h>
#include <cstdint>
#include <cfloat>

#define NTOK 32768
#define NEXP 64
#define CDIM 1024
#define CAPV 2048
#define BM   128
#define NCH  128          // K chunks of 8
#define THREADS 256
#define EPS_GAP 3e-4f

__device__ int g_top[2 * NTOK];
// pre-fragged w: [chunk 128][pass 2][ntile 8][lane 32] x float2  (tf32 bits in fp32 slots)
__device__ __align__(16) float g_bfrag[NCH * 1024];

typedef unsigned long long u64;

// ---------------------------------------------------------------------------
__device__ __forceinline__ uint32_t smem_u32(const void* p) {
    uint32_t a;
    asm("{ .reg .u64 t; cvta.to.shared.u64 t, %1; cvt.u32.u64 %0, t; }" : "=r"(a) : "l"(p));
    return a;
}
__device__ __forceinline__ uint32_t to_tf32(float f) {
    uint32_t r;
    asm("cvt.rna.tf32.f32 %0, %1;" : "=r"(r) : "f"(f));
    return r;
}
__device__ __forceinline__ void mma_tf32(float* d, const uint32_t* a, const uint32_t* b) {
    asm volatile(
        "mma.sync.aligned.m16n8k8.row.col.f32.tf32.tf32.f32 "
        "{%0,%1,%2,%3}, {%4,%5,%6,%7}, {%8,%9}, {%0,%1,%2,%3};"
        : "+f"(d[0]), "+f"(d[1]), "+f"(d[2]), "+f"(d[3])
        : "r"(a[0]), "r"(a[1]), "r"(a[2]), "r"(a[3]), "r"(b[0]), "r"(b[1]));
}
__device__ __forceinline__ void lds64(uint32_t& r0, uint32_t& r1, uint32_t addr) {
    asm volatile("ld.shared.v2.u32 {%0,%1}, [%2];" : "=r"(r0), "=r"(r1) : "r"(addr));
}

// ---------------------------------------------------------------------------
// Kernel 0: split w into tf32 hi/lo pre-fragged layout for mma B operand.
// B frag (m16n8k8 .col): lane l -> col n = ntile*8 + l/4, rows k = l%4, l%4+4.
// ---------------------------------------------------------------------------
__global__ __launch_bounds__(256) void wsplit_kernel(const float* __restrict__ w)
{
    int id = blockIdx.x * 256 + threadIdx.x;   // 0..65535 float2 slots
    int l = id & 31, t = (id >> 5) & 7, p = (id >> 8) & 1, c = id >> 9;
    int n  = t * 8 + (l >> 2);
    int k0 = c * 8 + (l & 3);
    float w0 = w[n * CDIM + k0];
    float w1 = w[n * CDIM + k0 + 4];
    uint32_t h0 = to_tf32(w0), h1 = to_tf32(w1);
    uint32_t v0, v1;
    if (p == 0) { v0 = h0; v1 = h1; }
    else {
        v0 = to_tf32(w0 - __uint_as_float(h0));
        v1 = to_tf32(w1 - __uint_as_float(h1));
    }
    reinterpret_cast<uint2*>(g_bfrag)[id] = make_uint2(v0, v1);
}

// ---------------------------------------------------------------------------
// Kernel 1: tf32 3-pass tensor GEMM (M=32768,N=64,K=1024) + fused top-2/softmax
// with near-tie detection and exact fp32 rescue for flagged rows.
// ---------------------------------------------------------------------------
__global__ __launch_bounds__(THREADS, 2) void gemm_top2_kernel(
    const float* __restrict__ x, const float* __restrict__ wglob,
    float* __restrict__ out_probs, float* __restrict__ out_idx)
{
    __shared__ __align__(16) float sbuf[4 * 1024];   // 4 stages x 4KB
    __shared__ int slist[128];
    __shared__ int scnt;

    const int tid  = threadIdx.x;
    const int wid  = tid >> 5;
    const int lane = tid & 31;
    const int gq   = lane >> 2;   // groupID
    const int q    = lane & 3;    // thread-in-group
    const int row0 = blockIdx.x * BM;

    if (tid == 0) scnt = 0;

    const uint32_t sb = smem_u32(sbuf);
    const float4* bsrc = reinterpret_cast<const float4*>(g_bfrag);

    const float* xp0 = x + (size_t)(row0 + wid * 16 + gq) * CDIM + q;
    const float* xp1 = xp0 + 8 * CDIM;

    auto cpa = [&](int c) {
        uint32_t dst = sb + ((c & 3) * 256 + tid) * 16;
        asm volatile("cp.async.cg.shared.global [%0], [%1], 16;"
                     :: "r"(dst), "l"(bsrc + c * 256 + tid));
        asm volatile("cp.async.commit_group;" ::: "memory");
    };

    float acc[32];
#pragma unroll
    for (int i = 0; i < 32; i++) acc[i] = 0.0f;

    float af[4], afn[4];
    af[0] = xp0[0]; af[1] = xp1[0]; af[2] = xp0[4]; af[3] = xp1[4];

    cpa(0); cpa(1); cpa(2);

#pragma unroll 1
    for (int c = 0; c < NCH; c++) {
        if (c < NCH - 2)
            asm volatile("cp.async.wait_group 2;" ::: "memory");
        else
            asm volatile("cp.async.wait_group 0;" ::: "memory");
        __syncthreads();
        if (c + 3 < NCH) cpa(c + 3);

        {
            int cc = (c + 1 < NCH) ? c + 1 : NCH - 1;
            const float* p0 = xp0 + cc * 8;
            const float* p1 = xp1 + cc * 8;
            afn[0] = p0[0]; afn[1] = p1[0]; afn[2] = p0[4]; afn[3] = p1[4];
        }

        uint32_t ahi[4], alo[4];
#pragma unroll
        for (int i = 0; i < 4; i++) {
            ahi[i] = to_tf32(af[i]);
            alo[i] = to_tf32(af[i] - __uint_as_float(ahi[i]));
        }

        const uint32_t bbase = sb + (c & 3) * 4096 + lane * 8;
        uint32_t bb[16];
#pragma unroll
        for (int t = 0; t < 8; t++) lds64(bb[2 * t], bb[2 * t + 1], bbase + t * 256);
#pragma unroll
        for (int t = 0; t < 8; t++) mma_tf32(acc + 4 * t, ahi, bb + 2 * t);
#pragma unroll
        for (int t = 0; t < 8; t++) mma_tf32(acc + 4 * t, alo, bb + 2 * t);
#pragma unroll
        for (int t = 0; t < 8; t++) lds64(bb[2 * t], bb[2 * t + 1], bbase + 2048 + t * 256);
#pragma unroll
        for (int t = 0; t < 8; t++) mma_tf32(acc + 4 * t, ahi, bb + 2 * t);

        af[0] = afn[0]; af[1] = afn[1]; af[2] = afn[2]; af[3] = afn[3];
    }

    // --- epilogue: per-row top-3 + near-tie flag; write safe rows ---
#pragma unroll
    for (int half = 0; half < 2; half++) {
        float a1 = -FLT_MAX, a2 = -FLT_MAX, a3 = -FLT_MAX;
        int j1 = 0, j2 = 0;
#pragma unroll
        for (int t = 0; t < 8; t++) {
#pragma unroll
            for (int cc = 0; cc < 2; cc++) {
                float v = acc[4 * t + 2 * half + cc];
                int jj = 8 * t + 2 * q + cc;
                if (v > a1)      { a3 = a2; a2 = a1; j2 = j1; a1 = v; j1 = jj; }
                else if (v > a2) { a3 = a2; a2 = v; j2 = jj; }
                else if (v > a3) { a3 = v; }
            }
        }
        // merge top-3 across the 4 lanes of this row (width-4 shfl)
#pragma unroll
        for (int o = 2; o > 0; o >>= 1) {
            float b1 = __shfl_down_sync(0xffffffffu, a1, o, 4);
            int   k1 = __shfl_down_sync(0xffffffffu, j1, o, 4);
            float b2 = __shfl_down_sync(0xffffffffu, a2, o, 4);
            int   k2 = __shfl_down_sync(0xffffffffu, j2, o, 4);
            float b3 = __shfl_down_sync(0xffffffffu, a3, o, 4);
            if (b1 > a1 || (b1 == a1 && k1 < j1)) {
                a3 = a2; a2 = a1; j2 = j1; a1 = b1; j1 = k1;
            } else if (b1 > a2 || (b1 == a2 && k1 < j2)) {
                a3 = a2; a2 = b1; j2 = k1;
            } else if (b1 > a3) a3 = b1;
            if (b2 > a2 || (b2 == a2 && k2 < j2)) {
                a3 = a2; a2 = b2; j2 = k2;
            } else if (b2 > a3) a3 = b2;
            if (b3 > a3) a3 = b3;
        }
        if (q == 0) {
            int row = wid * 16 + gq + half * 8;
            bool flag = (a1 - a2 < EPS_GAP) || (a2 - a3 < EPS_GAP);
            if (!flag) {
                int t = row0 + row;
                float ed = __expf(a2 - a1);
                float p1 = 1.0f / (1.0f + ed);
                float p2 = ed / (1.0f + ed);
                g_top[t]        = j1;
                g_top[NTOK + t] = j2;
                out_probs[2 * t]     = p1;
                out_probs[2 * t + 1] = p2;
                out_idx[2 * t]       = (float)j1;
                out_idx[2 * t + 1]   = (float)j2;
            } else {
                int slot = atomicAdd(&scnt, 1);
                slist[slot] = row;
            }
        }
    }

    // --- rescue: exact fp32 rescore of all 64 experts for flagged rows ---
    __syncthreads();
    const int nflag = scnt;
    for (int i = wid; i < nflag; i += 8) {
        int row = slist[i];
        const float4* xr = reinterpret_cast<const float4*>(x + (size_t)(row0 + row) * CDIM);
        const float4* wa = reinterpret_cast<const float4*>(wglob + (size_t)lane * CDIM);
        const float4* wb = reinterpret_cast<const float4*>(wglob + (size_t)(lane + 32) * CDIM);
        float s0 = 0.0f, s1 = 0.0f;
#pragma unroll 4
        for (int k = 0; k < CDIM / 4; k++) {
            float4 xv = xr[k], va = wa[k], vb = wb[k];
            s0 += xv.x * va.x; s0 += xv.y * va.y; s0 += xv.z * va.z; s0 += xv.w * va.w;
            s1 += xv.x * vb.x; s1 += xv.y * vb.y; s1 += xv.z * vb.z; s1 += xv.w * vb.w;
        }
        float a1, a2; int j1, j2;
        if (s0 >= s1) { a1 = s0; j1 = lane;      a2 = s1; j2 = lane + 32; }
        else          { a1 = s1; j1 = lane + 32; a2 = s0; j2 = lane;      }
#pragma unroll
        for (int o = 16; o > 0; o >>= 1) {
            float b1 = __shfl_down_sync(0xffffffffu, a1, o);
            int   k1 = __shfl_down_sync(0xffffffffu, j1, o);
            float b2 = __shfl_down_sync(0xffffffffu, a2, o);
            int   k2 = __shfl_down_sync(0xffffffffu, j2, o);
            bool first = (a1 > b1) || (a1 == b1 && j1 < k1);
            if (first) {
                bool s = (a2 > b1) || (a2 == b1 && j2 < k1);
                if (!s) { a2 = b1; j2 = k1; }
            } else {
                bool s = (b2 > a1) || (b2 == a1 && k2 < j1);
                if (s) { a1 = b1; j1 = k1; a2 = b2; j2 = k2; }
                else   { a2 = a1; j2 = j1; a1 = b1; j1 = k1; }
            }
        }
        if (lane == 0) {
            int t = row0 + row;
            float ed = __expf(a2 - a1);
            float p1 = 1.0f / (1.0f + ed);
            float p2 = ed / (1.0f + ed);
            g_top[t]        = j1;
            g_top[NTOK + t] = j2;
            out_probs[2 * t]     = p1;
            out_probs[2 * t + 1] = p2;
            out_idx[2 * t]       = (float)j1;
            out_idx[2 * t + 1]   = (float)j2;
        }
    }
}

// ---------------------------------------------------------------------------
// Kernel 2: rank/capacity. 128 CTAs: e = bid>>1, s = bid&1. Coalesced loads.
// Single packed block scan (8 chunk-counts in two u64s, 16-bit fields).
// ---------------------------------------------------------------------------
__global__ __launch_bounds__(1024) void rank_kernel(
    float* __restrict__ out_mask, float* __restrict__ out_probs,
    float* __restrict__ out_rank)
{
    const int e    = blockIdx.x >> 1;
    const int s    = blockIdx.x & 1;
    const int tid  = threadIdx.x;
    const int lane = tid & 31;
    const int wid  = tid >> 5;

    __shared__ u64 wsA[32], wsB[32];
    __shared__ uint32_t ws0[32];
    __shared__ u64 btA, btB;
    __shared__ uint32_t bt0;

    const int4* p = reinterpret_cast<const int4*>(g_top + s * NTOK);
    int4 v[8];
#pragma unroll
    for (int i = 0; i < 8; i++) v[i] = p[i * 1024 + tid];

    int cnt[8];
#pragma unroll
    for (int i = 0; i < 8; i++)
        cnt[i] = (v[i].x == e) + (v[i].y == e) + (v[i].z == e) + (v[i].w == e);

    u64 packA = (u64)cnt[0] | ((u64)cnt[1] << 16) | ((u64)cnt[2] << 32) | ((u64)cnt[3] << 48);
    u64 packB = (u64)cnt[4] | ((u64)cnt[5] << 16) | ((u64)cnt[6] << 32) | ((u64)cnt[7] << 48);

    uint32_t c0 = 0;
    if (s) {
        const int4* p0 = reinterpret_cast<const int4*>(g_top);
#pragma unroll
        for (int i = 0; i < 8; i++) {
            int4 u = p0[i * 1024 + tid];
            c0 += (u.x == e) + (u.y == e) + (u.z == e) + (u.w == e);
        }
    }

    u64 iA = packA, iB = packB;
    uint32_t iz = c0;
#pragma unroll
    for (int o = 1; o < 32; o <<= 1) {
        u64 tA = __shfl_up_sync(0xffffffffu, iA, o);
        u64 tB = __shfl_up_sync(0xffffffffu, iB, o);
        uint32_t tz = __shfl_up_sync(0xffffffffu, iz, o);
        if (lane >= o) { iA += tA; iB += tB; iz += tz; }
    }
    if (lane == 31) { wsA[wid] = iA; wsB[wid] = iB; ws0[wid] = iz; }
    __syncthreads();

    if (wid == 0) {
        u64 a = wsA[lane], b = wsB[lane];
        uint32_t z = ws0[lane];
        u64 ja = a, jb = b;
        uint32_t jz = z;
#pragma unroll
        for (int o = 1; o < 32; o <<= 1) {
            u64 tA = __shfl_up_sync(0xffffffffu, ja, o);
            u64 tB = __shfl_up_sync(0xffffffffu, jb, o);
            uint32_t tz = __shfl_up_sync(0xffffffffu, jz, o);
            if (lane >= o) { ja += tA; jb += tB; jz += tz; }
        }
        wsA[lane] = ja - a;
        wsB[lane] = jb - b;
        if (lane == 31) { btA = ja; btB = jb; bt0 = jz; }
    }
    __syncthreads();

    u64 exA = wsA[wid] + (iA - packA);
    u64 exB = wsB[wid] + (iB - packB);
    u64 tA = btA, tB = btB;

    int base = s ? (int)bt0 : 0;
#pragma unroll
    for (int i = 0; i < 8; i++) {
        int ex  = (int)((i < 4 ? (exA >> (16 * i)) : (exB >> (16 * (i - 4)))) & 0xffffu);
        int tot = (int)((i < 4 ? (tA  >> (16 * i)) : (tB  >> (16 * (i - 4)))) & 0xffffu);
        int r = base + ex;
        int g = i * 1024 + tid;
        int vals[4] = {v[i].x, v[i].y, v[i].z, v[i].w};
#pragma unroll
        for (int j = 0; j < 4; j++) {
            if (vals[j] == e) {
                int oi = (4 * g + j) * 2 + s;
                out_rank[oi] = (float)r;
                if (r < CAPV) out_mask[(size_t)oi * NEXP + e] = 1.0f;
                else out_probs[oi] = 0.0f;
                r++;
            }
        }
        base += tot;
    }
}

// ---------------------------------------------------------------------------
extern "C" void kernel_launch(void* const* d_in, const int* in_sizes, int n_in,
                              void* d_out, int out_size)
{
    const float* x = (const float*)d_in[0];
    const float* w = (const float*)d_in[1];

    float* out       = (float*)d_out;
    float* out_mask  = out;                                   // N*2*64
    float* out_probs = out + (size_t)NTOK * 2 * NEXP;         // N*2
    float* out_idx   = out_probs + NTOK * 2;                  // N*2
    float* out_rank  = out_idx + NTOK * 2;                    // N*2

    wsplit_kernel<<<256, 256>>>(w);
    cudaMemsetAsync(out_mask, 0, (size_t)NTOK * 2 * NEXP * sizeof(float));
    gemm_top2_kernel<<<NTOK / BM, THREADS>>>(x, w, out_probs, out_idx);
    rank_kernel<<<2 * NEXP, 1024>>>(out_mask, out_probs, out_rank);
}